// round 13
// baseline (speedup 1.0000x reference)
#include <cuda_runtime.h>
#include <cuda_bf16.h>
#include <cuda_fp16.h>
#include <math_constants.h>
#include <cstdint>

#define Bc 2
#define Tc 2048
#define Dc 1024
#define Hc 16
#define HDc 64
#define Mc (Bc*Tc)

#define KTOT 3072          // tripled K for split-bf16 3-product GEMM
#define BM 128
#define BN 256
#define BK 32
#define LDS_ROW 40
#define A_STG (BM*LDS_ROW*2)              // 10240
#define B_STG (BN*LDS_ROW*2)              // 20480
#define STG_BYTES (A_STG+B_STG)           // 30720
#define STAGES 4
#define SMEM_DYN (STAGES*STG_BYTES)       // 122880

// attention tiling
#define AT_M 128
#define LDSA 200
#define LDV  72
#define SG_BYTES_A (128*LDSA*2)           // 51200
#define K2STG (64*LDSA*2)                 // 25600
#define VTSTG (64*LDV*2)                  // 9216
#define ASMEM (SG_BYTES_A + 2*K2STG + 2*VTSTG)  // 120832

// ---------------- scratch (device globals; no runtime allocation) ----------
__device__ __align__(16) float g_q[Bc*Hc*Tc*HDc];      // (b,h,t,hd) fp32
__device__ __align__(16) float g_ksum[Bc*Hc*HDc];
__device__ __align__(16) float g_gdiag[Hc*HDc];
__device__ __align__(16) float g_bqk[2*Dc];
__device__ __align__(16) __nv_bfloat16 g_x2[Mc*KTOT];        // [hi|hi|lo] of x (bf16)
__device__ __align__(16) __half g_xh[Mc*1024];               // fp16(x)
__device__ __align__(16) __nv_bfloat16 g_w2[2][Dc*KTOT];     // [hi|lo|hi] Wq,Wk
__device__ __align__(16) __half g_wv[Dc*1024];               // fp16(Wv)
__device__ __align__(16) __half g_wo[Dc*1024];               // fp16(Wo)
__device__ __align__(16) __half g_o2h[Mc*1024];              // fp16 attn out
__device__ __align__(16) __nv_bfloat16 g_k2[Bc*Hc*Tc*192];   // [hi|lo|hi] key rows
__device__ __align__(16) __half g_v2t[Bc*Hc*HDc*Tc];         // [bh][d][t] fp16 V^T

// ---------------- PTX helpers ----------------------------------------------
__device__ __forceinline__ uint32_t smem_u32(const void* p) {
    uint32_t a;
    asm("{ .reg .u64 t; cvta.to.shared.u64 t, %1; cvt.u32.u64 %0, t; }" : "=r"(a) : "l"(p));
    return a;
}
#define CP_ASYNC16(sm, gm) \
    asm volatile("cp.async.cg.shared.global [%0], [%1], 16;" :: "r"(sm), "l"(gm))
#define CP_COMMIT() asm volatile("cp.async.commit_group;" ::: "memory")
#define CP_WAIT(n)  asm volatile("cp.async.wait_group %0;" :: "n"(n) : "memory")

__device__ __forceinline__ void ldsm_x4(uint32_t& r0, uint32_t& r1,
                                        uint32_t& r2, uint32_t& r3, uint32_t addr) {
    asm volatile("ldmatrix.sync.aligned.m8n8.x4.shared.b16 {%0,%1,%2,%3}, [%4];"
                 : "=r"(r0), "=r"(r1), "=r"(r2), "=r"(r3) : "r"(addr));
}
__device__ __forceinline__ void mma_bf(float* c, const uint32_t* a, const uint32_t* b) {
    asm volatile(
        "mma.sync.aligned.m16n8k16.row.col.f32.bf16.bf16.f32 "
        "{%0,%1,%2,%3}, {%4,%5,%6,%7}, {%8,%9}, {%0,%1,%2,%3};"
        : "+f"(c[0]), "+f"(c[1]), "+f"(c[2]), "+f"(c[3])
        : "r"(a[0]), "r"(a[1]), "r"(a[2]), "r"(a[3]), "r"(b[0]), "r"(b[1]));
}
__device__ __forceinline__ void mma_hf(float* c, const uint32_t* a, const uint32_t* b) {
    asm volatile(
        "mma.sync.aligned.m16n8k16.row.col.f32.f16.f16.f32 "
        "{%0,%1,%2,%3}, {%4,%5,%6,%7}, {%8,%9}, {%0,%1,%2,%3};"
        : "+f"(c[0]), "+f"(c[1]), "+f"(c[2]), "+f"(c[3])
        : "r"(a[0]), "r"(a[1]), "r"(a[2]), "r"(a[3]), "r"(b[0]), "r"(b[1]));
}
__device__ __forceinline__ uint32_t pkhf(float lo, float hi) {
    uint32_t r;
    asm("cvt.rn.f16x2.f32 %0, %1, %2;" : "=r"(r) : "f"(hi), "f"(lo));
    return r;
}

// ---------------------------------------------------------------------------
// One prep kernel: x -> bf16 triple + fp16 plane; Wq/Wk -> bf16 triples;
// Wv/Wo -> fp16 planes; bias concat; gdiag; ksum zero.
// ---------------------------------------------------------------------------
__global__ void prep_all(const float* __restrict__ x,
                         const float* __restrict__ Wq, const float* __restrict__ Wk,
                         const float* __restrict__ Wv, const float* __restrict__ Wo,
                         const float* __restrict__ bq, const float* __restrict__ bk,
                         const float* __restrict__ A, const float* __restrict__ ll) {
    int i = blockIdx.x * blockDim.x + threadIdx.x;
    const int N0 = Mc * 512, NW = Dc * 512;
    if (i < N0) {                               // x: triple + fp16
        float2 v = ((const float2*)x)[i];
        int r = i >> 9, c2 = i & 511;
        __nv_bfloat162 hi, lo;
        hi.x = __float2bfloat16(v.x); hi.y = __float2bfloat16(v.y);
        lo.x = __float2bfloat16(v.x - __bfloat162float(hi.x));
        lo.y = __float2bfloat16(v.y - __bfloat162float(hi.y));
        __nv_bfloat162* d = (__nv_bfloat162*)(g_x2 + (size_t)r * KTOT);
        d[c2] = hi; d[512 + c2] = hi; d[1024 + c2] = lo;
        __half2 h; h.x = __float2half_rn(v.x); h.y = __float2half_rn(v.y);
        ((__half2*)(g_xh + (size_t)r * 1024))[c2] = h;
        return;
    }
    i -= N0;
    if (i < 2 * NW) {                           // Wq / Wk bf16 triple [hi|lo|hi]
        const float* W = (i < NW) ? Wq : Wk;
        __nv_bfloat16* dst = (i < NW) ? g_w2[0] : g_w2[1];
        int j = (i < NW) ? i : i - NW;
        float2 v = ((const float2*)W)[j];
        int r = j >> 9, c2 = j & 511;
        __nv_bfloat162 hi, lo;
        hi.x = __float2bfloat16(v.x); hi.y = __float2bfloat16(v.y);
        lo.x = __float2bfloat16(v.x - __bfloat162float(hi.x));
        lo.y = __float2bfloat16(v.y - __bfloat162float(hi.y));
        __nv_bfloat162* d = (__nv_bfloat162*)(dst + (size_t)r * KTOT);
        d[c2] = hi; d[512 + c2] = lo; d[1024 + c2] = hi;
        return;
    }
    i -= 2 * NW;
    if (i < 2 * NW) {                           // Wv / Wo fp16 plane
        const float* W = (i < NW) ? Wv : Wo;
        __half* dst = (i < NW) ? g_wv : g_wo;
        int j = (i < NW) ? i : i - NW;
        float2 v = ((const float2*)W)[j];
        int r = j >> 9, c2 = j & 511;
        __half2 h; h.x = __float2half_rn(v.x); h.y = __float2half_rn(v.y);
        ((__half2*)(dst + (size_t)r * 1024))[c2] = h;
        return;
    }
    i -= 2 * NW;
    if (i < 2 * Dc) {                           // bias concat
        g_bqk[i] = (i < Dc) ? bq[i] : bk[i - Dc];
        return;
    }
    i -= 2 * Dc;
    if (i < Hc * HDc) {                         // gdiag
        int h = i >> 6, d = i & 63;
        float s = expf(ll[h]);
#pragma unroll
        for (int r = 0; r < 16; r++) {
            float a = A[(h * 16 + r) * HDc + d];
            s = fmaf(a, a, s);
        }
        g_gdiag[i] = s;
        return;
    }
    i -= Hc * HDc;
    if (i < Bc * Hc * HDc) g_ksum[i] = 0.f;     // zero for ksum atomics
}
#define PREP_TOTAL (Mc*512 + 4*(Dc*512) + 2*Dc + Hc*HDc + Bc*Hc*HDc)

// ---------------------------------------------------------------------------
// GEMM body: tile 128x256, warp 64x64, BK=32, 4-stage cp.async.
// mode 0: QK (n0>>10: q fp32 / k triple); mode 1: -> Yext; mode 2: V plane.
// ---------------------------------------------------------------------------
template<int FP16M>
__device__ __forceinline__ void gemm_body(
    uint32_t base, const char* gAb, const char* gWb,
    const float* __restrict__ bias, float* __restrict__ Yext,
    int mode, int ktot, int m0, int n0)
{
    int tid = threadIdx.x, wid = tid >> 5, lane = tid & 31;
    int wm = wid & 1, wn = wid >> 1;

    const char* gA = gAb + (size_t)m0 * ktot * 2;
    const char* gW = gWb + (size_t)n0 * ktot * 2;
    size_t kstride = (size_t)ktot * 2;

    auto load_chunk = [&](int c) {
        uint32_t sa = base + (c % STAGES) * STG_BYTES;
        uint32_t sb = sa + A_STG;
        size_t k0 = (size_t)c * (BK * 2);
#pragma unroll
        for (int it = 0; it < 2; it++) {
            int ch = tid + it * 256;
            int r = ch >> 2, off = (ch & 3) * 16;
            CP_ASYNC16(sa + r * (LDS_ROW*2) + off, gA + r * kstride + k0 + off);
        }
#pragma unroll
        for (int it = 0; it < 4; it++) {
            int ch = tid + it * 256;
            int r = ch >> 2, off = (ch & 3) * 16;
            CP_ASYNC16(sb + r * (LDS_ROW*2) + off, gW + r * kstride + k0 + off);
        }
        CP_COMMIT();
    };

    float acc[4][8][4];
#pragma unroll
    for (int i = 0; i < 4; i++)
#pragma unroll
        for (int j = 0; j < 8; j++)
#pragma unroll
            for (int l = 0; l < 4; l++) acc[i][j][l] = 0.f;

    load_chunk(0);
    load_chunk(1);
    load_chunk(2);

    int a_row = wm * 64 + (lane & 15);
    int a_col8 = (lane >> 4) * 8;
    int b_row = wn * 64 + (lane & 7) + ((lane >> 4) << 3);
    int b_col8 = ((lane >> 3) & 1) * 8;
    int nk = ktot / BK;

#pragma unroll 1
    for (int i = 0; i < nk; i++) {
        CP_WAIT(STAGES - 2);
        __syncthreads();
        if (i + STAGES - 1 < nk) load_chunk(i + STAGES - 1);

        uint32_t sa = base + (i % STAGES) * STG_BYTES;
        uint32_t sb = sa + A_STG;
#pragma unroll
        for (int kk = 0; kk < 2; kk++) {
            uint32_t a[4][4], b[8][2];
#pragma unroll
            for (int mf = 0; mf < 4; mf++)
                ldsm_x4(a[mf][0], a[mf][1], a[mf][2], a[mf][3],
                        sa + ((a_row + mf*16) * LDS_ROW + kk*16 + a_col8) * 2);
#pragma unroll
            for (int np = 0; np < 4; np++)
                ldsm_x4(b[2*np][0], b[2*np][1], b[2*np+1][0], b[2*np+1][1],
                        sb + ((b_row + np*16) * LDS_ROW + kk*16 + b_col8) * 2);
#pragma unroll
            for (int mf = 0; mf < 4; mf++)
#pragma unroll
                for (int nf = 0; nf < 8; nf++) {
                    if (FP16M) mma_hf(acc[mf][nf], a[mf], b[nf]);
                    else       mma_bf(acc[mf][nf], a[mf], b[nf]);
                }
        }
    }

    int proj = n0 >> 10;
#pragma unroll
    for (int mf = 0; mf < 4; mf++) {
#pragma unroll
        for (int nf = 0; nf < 8; nf++) {
            int m = m0 + wm*64 + mf*16 + (lane >> 2);
            int n = n0 + wn*64 + nf*8 + 2*(lane & 3);
            float b0 = bias[n], b1 = bias[n+1];
#pragma unroll
            for (int half = 0; half < 2; half++) {
                int mm = m + half * 8;
                float v0 = acc[mf][nf][half*2+0] + b0;
                float v1 = acc[mf][nf][half*2+1] + b1;
                int bb = mm >> 11, t = mm & 2047;
                int nn = n & 1023;
                int h = nn >> 6, d = nn & 63;
                int bh = bb * Hc + h;
                if (mode == 1) {
                    *(float2*)(Yext + (size_t)mm * Dc + n) = make_float2(v0, v1);
                } else if (mode == 2) {
                    __half* pbase = g_v2t + (size_t)bh * HDc * Tc;
                    pbase[(size_t)d * Tc + t]     = __float2half_rn(v0);
                    pbase[(size_t)(d+1) * Tc + t] = __float2half_rn(v1);
                } else if (proj == 0) {
                    *(float2*)(g_q + ((size_t)bh * Tc + t) * HDc + d) =
                        make_float2(v0, v1);
                } else {
                    __nv_bfloat16 h0 = __float2bfloat16(v0);
                    __nv_bfloat16 l0 = __float2bfloat16(v0 - __bfloat162float(h0));
                    __nv_bfloat16 h1 = __float2bfloat16(v1);
                    __nv_bfloat16 l1 = __float2bfloat16(v1 - __bfloat162float(h1));
                    __nv_bfloat16* row = g_k2 + ((size_t)bh * Tc + t) * 192;
                    row[d] = h0;   row[d+1] = h1;
                    row[64+d] = l0; row[64+d+1] = l1;
                    row[128+d] = h0; row[128+d+1] = h1;
                }
            }
        }
    }
}

// fused QKV: y<8 -> QK bf16 3-product (K=3072); y>=8 -> V fp16 (K=1024)
__global__ __launch_bounds__(256)
void qkv_fused(const float* __restrict__ bv) {
    extern __shared__ __align__(16) char dsmem[];
    uint32_t base = smem_u32(dsmem);
    int by = blockIdx.y;
    if (by < 8)
        gemm_body<0>(base, (const char*)g_x2, (const char*)g_w2,
                     g_bqk, nullptr, 0, KTOT, blockIdx.x * BM, by * 256);
    else
        gemm_body<1>(base, (const char*)g_xh, (const char*)g_wv,
                     bv, nullptr, 2, 1024, blockIdx.x * BM, (by - 8) * 256);
}

// final projection: out = o2h @ Wo^T + bo  (fp16 single product, K=1024)
__global__ __launch_bounds__(256)
void gemm_o(const float* __restrict__ bo, float* __restrict__ out) {
    extern __shared__ __align__(16) char dsmem[];
    uint32_t base = smem_u32(dsmem);
    gemm_body<1>(base, (const char*)g_o2h, (const char*)g_wo,
                 bo, out, 1, 1024, blockIdx.x * BM, blockIdx.y * 256);
}

// ---------------------------------------------------------------------------
// ksum over 256 blocks with atomics (g_ksum zeroed by prep_all)
// ---------------------------------------------------------------------------
__global__ __launch_bounds__(256) void ksum2_kernel() {
    __shared__ float red[256];
    int bh = blockIdx.x;
    int seg = blockIdx.y;
    int d = threadIdx.x & 63, chunk = threadIdx.x >> 6;
    const __nv_bfloat16* base = g_k2 + (size_t)bh * Tc * 192;
    float s = 0.f;
    int t0 = seg * 256 + chunk * 64;
    for (int t = t0; t < t0 + 64; t++) {
        const __nv_bfloat16* row = base + (size_t)t * 192;
        s += __bfloat162float(row[d]) + __bfloat162float(row[64 + d]);
    }
    red[threadIdx.x] = s;
    __syncthreads();
    if (chunk == 0)
        atomicAdd(&g_ksum[bh * HDc + d],
                  red[d] + red[64 + d] + red[128 + d] + red[192 + d]);
}

// ---------------------------------------------------------------------------
// Tensor-core flash attention, software-pipelined: QK(t+1) mma issued
// interleaved at source level with softmax(t) ALU slices, so the tensor
// pipe stays busy through the softmax phase. s-register double buffer.
// ---------------------------------------------------------------------------
__global__ __launch_bounds__(256, 1)
void attn_tc() {
    extern __shared__ __align__(16) char asmem[];
    uint32_t sgs = smem_u32(asmem);
    uint32_t k2s = sgs + SG_BYTES_A;
    uint32_t vts = k2s + 2 * K2STG;
    __nv_bfloat16* sg_sm = (__nv_bfloat16*)asmem;

    int tid = threadIdx.x, wid = tid >> 5, lane = tid & 31;
    int bh = blockIdx.y, h = bh & 15, b = bh >> 4;
    int q0 = blockIdx.x * AT_M;

    const float*         q_g = g_q   + ((size_t)bh * Tc + q0) * HDc;
    const __nv_bfloat16* k_g = g_k2  + (size_t)bh * Tc * 192;
    const __half*        v_g = g_v2t + (size_t)bh * HDc * Tc;
    const float*         ks  = g_ksum + bh * HDc;
    const float*         gd  = g_gdiag + h * HDc;

    auto load_tile = [&](int ti) {
        int st = ti & 1;
        int j0 = ti * 64;
        uint32_t kd = k2s + st * K2STG;
        uint32_t vd = vts + st * VTSTG;
#pragma unroll
        for (int it = 0; it < 6; it++) {          // K: 64 x 192 bf16
            int id = tid + it * 256;
            int r = id / 24, c = id % 24;
            CP_ASYNC16(kd + r * (LDSA*2) + c * 16,
                       (const char*)(k_g + (size_t)(j0 + r) * 192 + c * 8));
        }
#pragma unroll
        for (int it = 0; it < 2; it++) {          // V^T: 64 x 64 fp16
            int id = tid + it * 256;
            int r = id >> 3, c = id & 7;
            CP_ASYNC16(vd + r * (LDV*2) + c * 16,
                       (const char*)(v_g + (size_t)r * Tc + j0 + c * 8));
        }
        CP_COMMIT();
    };

    load_tile(0);
    load_tile(1);

    // compute Sg tile in-kernel: [hi|hi|lo] rows of LDSA
    for (int idx = tid; idx < 128 * 64; idx += 256) {
        int r = idx >> 6, d = idx & 63;
        float sg = (2048.0f * q_g[r * HDc + d] - ks[d]) * gd[d];
        __nv_bfloat16 hi = __float2bfloat16(sg);
        __nv_bfloat16 lo = __float2bfloat16(sg - __bfloat162float(hi));
        __nv_bfloat16* row = sg_sm + r * LDSA;
        row[d] = hi; row[64 + d] = hi; row[128 + d] = lo;
    }
    __syncthreads();

    uint32_t aq[12][4];
    {
        int arow = wid * 16 + (lane & 15);
        int acol = (lane >> 4) * 8;
#pragma unroll
        for (int kc = 0; kc < 12; kc++)
            ldsm_x4(aq[kc][0], aq[kc][1], aq[kc][2], aq[kc][3],
                    sgs + (arow * LDSA + kc * 16 + acol) * 2);
    }

    float o_acc[8][4];
#pragma unroll
    for (int nf = 0; nf < 8; nf++)
#pragma unroll
        for (int l = 0; l < 4; l++) o_acc[nf][l] = 0.f;
    float m0 = -CUDART_INF_F, m1 = -CUDART_INF_F, l0 = 0.f, l1 = 0.f;

    int brow = (lane & 7) + ((lane >> 4) << 3);
    int bcol8 = ((lane >> 3) & 1) * 8;

    CP_WAIT(1);
    __syncthreads();

    float sA[8][4], sB[8][4];
    uint32_t Ahi[4][4];

    // prologue: QK(0) -> sA (tile 0, buffer 0)
    {
#pragma unroll
        for (int nf = 0; nf < 8; nf++)
#pragma unroll
            for (int l = 0; l < 4; l++) sA[nf][l] = 0.f;
#pragma unroll
        for (int kc = 0; kc < 12; kc++) {
            uint32_t bq[8][2];
#pragma unroll
            for (int np = 0; np < 4; np++)
                ldsm_x4(bq[2*np][0], bq[2*np][1], bq[2*np+1][0], bq[2*np+1][1],
                        k2s + ((np*16 + brow) * LDSA + kc*16 + bcol8) * 2);
#pragma unroll
            for (int nf = 0; nf < 8; nf++)
                mma_bf(sA[nf], aq[kc], bq[nf]);
        }
    }

    // iteration body: softmax(t) on s_cur interleaved with QK(t+1) -> s_nxt
    auto body = [&](int t, float (&s_cur)[8][4], float (&s_nxt)[8][4]) {
        const bool qk = (t < 31);
        CP_WAIT(0);
        __syncthreads();
        uint32_t kd_next = k2s + ((t + 1) & 1) * K2STG;
        uint32_t vd = vts + (t & 1) * VTSTG;

        if (qk) {
#pragma unroll
            for (int nf = 0; nf < 8; nf++)
#pragma unroll
                for (int l = 0; l < 4; l++) s_nxt[nf][l] = 0.f;
        }

#define QKC(kc) \
        if (qk) { \
            uint32_t bq[8][2]; \
            _Pragma("unroll") \
            for (int np = 0; np < 4; np++) \
                ldsm_x4(bq[2*np][0], bq[2*np][1], bq[2*np+1][0], bq[2*np+1][1], \
                        kd_next + ((np*16 + brow) * LDSA + (kc)*16 + bcol8) * 2); \
            _Pragma("unroll") \
            for (int nf = 0; nf < 8; nf++) mma_bf(s_nxt[nf], aq[kc], bq[nf]); \
        }
#define EXPPAIR(p) { \
            const int f0 = 2*(p), f1 = 2*(p)+1; \
            s_cur[f0][0] = __expf(s_cur[f0][0] - mn0); \
            s_cur[f0][1] = __expf(s_cur[f0][1] - mn0); \
            s_cur[f0][2] = __expf(s_cur[f0][2] - mn1); \
            s_cur[f0][3] = __expf(s_cur[f0][3] - mn1); \
            s_cur[f1][0] = __expf(s_cur[f1][0] - mn0); \
            s_cur[f1][1] = __expf(s_cur[f1][1] - mn0); \
            s_cur[f1][2] = __expf(s_cur[f1][2] - mn1); \
            s_cur[f1][3] = __expf(s_cur[f1][3] - mn1); \
            rs0 += s_cur[f0][0] + s_cur[f0][1] + s_cur[f1][0] + s_cur[f1][1]; \
            rs1 += s_cur[f0][2] + s_cur[f0][3] + s_cur[f1][2] + s_cur[f1][3]; \
            Ahi[p][0] = pkhf(s_cur[f0][0], s_cur[f0][1]); \
            Ahi[p][1] = pkhf(s_cur[f0][2], s_cur[f0][3]); \
            Ahi[p][2] = pkhf(s_cur[f1][0], s_cur[f1][1]); \
            Ahi[p][3] = pkhf(s_cur[f1][2], s_cur[f1][3]); }

        QKC(0)
        QKC(1)
        float rm0 = -CUDART_INF_F, rm1 = -CUDART_INF_F;
#pragma unroll
        for (int nf = 0; nf < 4; nf++) {
            rm0 = fmaxf(rm0, fmaxf(s_cur[nf][0], s_cur[nf][1]));
            rm1 = fmaxf(rm1, fmaxf(s_cur[nf][2], s_cur[nf][3]));
        }
        QKC(2)
#pragma unroll
        for (int nf = 4; nf < 8; nf++) {
            rm0 = fmaxf(rm0, fmaxf(s_cur[nf][0], s_cur[nf][1]));
            rm1 = fmaxf(rm1, fmaxf(s_cur[nf][2], s_cur[nf][3]));
        }
        QKC(3)
        rm0 = fmaxf(rm0, __shfl_xor_sync(0xffffffffu, rm0, 1));
        rm0 = fmaxf(rm0, __shfl_xor_sync(0xffffffffu, rm0, 2));
        rm1 = fmaxf(rm1, __shfl_xor_sync(0xffffffffu, rm1, 1));
        rm1 = fmaxf(rm1, __shfl_xor_sync(0xffffffffu, rm1, 2));
        QKC(4)
        float mn0 = fmaxf(m0, rm0), mn1 = fmaxf(m1, rm1);
        float sc0 = __expf(m0 - mn0), sc1 = __expf(m1 - mn1);
        m0 = mn0; m1 = mn1;
        float rs0 = 0.f, rs1 = 0.f;
        QKC(5)
        EXPPAIR(0)
        QKC(6)
        EXPPAIR(1)
        QKC(7)
        EXPPAIR(2)
        QKC(8)
        EXPPAIR(3)
        QKC(9)
        rs0 += __shfl_xor_sync(0xffffffffu, rs0, 1);
        rs0 += __shfl_xor_sync(0xffffffffu, rs0, 2);
        rs1 += __shfl_xor_sync(0xffffffffu, rs1, 1);
        rs1 += __shfl_xor_sync(0xffffffffu, rs1, 2);
        l0 = l0 * sc0 + rs0;
        l1 = l1 * sc1 + rs1;
        QKC(10)
#pragma unroll
        for (int nf = 0; nf < 8; nf++) {
            o_acc[nf][0] *= sc0; o_acc[nf][1] *= sc0;
            o_acc[nf][2] *= sc1; o_acc[nf][3] *= sc1;
        }
        QKC(11)
#undef QKC
#undef EXPPAIR

        // PV(t): o += P(t) * Vhi(t)
#pragma unroll
        for (int kc = 0; kc < 4; kc++) {
            uint32_t bvh[8][2];
#pragma unroll
            for (int np = 0; np < 4; np++)
                ldsm_x4(bvh[2*np][0], bvh[2*np][1], bvh[2*np+1][0], bvh[2*np+1][1],
                        vd + ((np*16 + brow) * LDV + kc*16 + bcol8) * 2);
#pragma unroll
            for (int nf = 0; nf < 8; nf++)
                mma_hf(o_acc[nf], Ahi[kc], bvh[nf]);
        }
        __syncthreads();
        if (t + 2 < 32) load_tile(t + 2);
    };

#pragma unroll 1
    for (int tp = 0; tp < 16; tp++) {
        body(2 * tp,     sA, sB);
        body(2 * tp + 1, sB, sA);
    }

    // epilogue: fp16 plane
    float inv0 = 1.0f / l0, inv1 = 1.0f / l1;
    int r0 = q0 + wid * 16 + (lane >> 2);
    int r1 = r0 + 8;
    __half* row0 = g_o2h + (size_t)(b * Tc + r0) * 1024;
    __half* row1 = g_o2h + (size_t)(b * Tc + r1) * 1024;
#pragma unroll
    for (int nf = 0; nf < 8; nf++) {
        int n = h * HDc + nf * 8 + 2 * (lane & 3);
        *(uint32_t*)(row0 + n) = pkhf(o_acc[nf][0] * inv0, o_acc[nf][1] * inv0);
        *(uint32_t*)(row1 + n) = pkhf(o_acc[nf][2] * inv1, o_acc[nf][3] * inv1);
    }
}

// ---------------------------------------------------------------------------
extern "C" void kernel_launch(void* const* d_in, const int* in_sizes, int n_in,
                              void* d_out, int out_size) {
    const float* x   = (const float*)d_in[0];
    const float* Wq  = (const float*)d_in[1];
    const float* bq  = (const float*)d_in[2];
    const float* Wk  = (const float*)d_in[3];
    const float* bk  = (const float*)d_in[4];
    const float* Wv  = (const float*)d_in[5];
    const float* bv  = (const float*)d_in[6];
    const float* Wo  = (const float*)d_in[7];
    const float* bo  = (const float*)d_in[8];
    const float* A   = (const float*)d_in[9];
    const float* ll  = (const float*)d_in[10];
    float* out = (float*)d_out;

    cudaFuncSetAttribute(qkv_fused, cudaFuncAttributeMaxDynamicSharedMemorySize, SMEM_DYN);
    cudaFuncSetAttribute(gemm_o,    cudaFuncAttributeMaxDynamicSharedMemorySize, SMEM_DYN);
    cudaFuncSetAttribute(attn_tc,   cudaFuncAttributeMaxDynamicSharedMemorySize, ASMEM);

    prep_all<<<(PREP_TOTAL + 255)/256, 256>>>(x, Wq, Wk, Wv, Wo, bq, bk, A, ll);

    // fused QK (bf16 3-product) + V (fp16 single product)
    qkv_fused<<<dim3(Mc/BM, 12), 256, SMEM_DYN>>>(bv);

    ksum2_kernel<<<dim3(Bc*Hc, 8), 256>>>();

    attn_tc<<<dim3(Tc / AT_M, Bc * Hc), 256, ASMEM>>>();

    gemm_o<<<dim3(Mc/BM, Dc/BN), 256, SMEM_DYN>>>(bo, out);
}

// round 17
// speedup vs baseline: 1.1125x; 1.1125x over previous
#include <cuda_runtime.h>
#include <cuda_bf16.h>
#include <cuda_fp16.h>
#include <math_constants.h>
#include <cstdint>

#define Bc 2
#define Tc 2048
#define Dc 1024
#define Hc 16
#define HDc 64
#define Mc (Bc*Tc)

#define KTOT 3072          // tripled K for split-bf16 3-product GEMM
#define BM 128
#define BN 256
#define BK 32
#define LDS_ROW 40
#define A_STG (BM*LDS_ROW*2)              // 10240
#define B_STG (BN*LDS_ROW*2)              // 20480
#define STG_BYTES (A_STG+B_STG)           // 30720
#define STAGES 4
#define SMEM_DYN (STAGES*STG_BYTES)       // 122880

// attention tiling
#define AT_M 128
#define LDSA 200
#define LDV  72
#define SG_BYTES_A (128*LDSA*2)           // 51200
#define K2STG (64*LDSA*2)                 // 25600
#define VTSTG (64*LDV*2)                  // 9216
#define ASMEM (SG_BYTES_A + 2*K2STG + 2*VTSTG)  // 120832

#define L2E 1.4426950408889634f

// ---------------- scratch (device globals; no runtime allocation) ----------
__device__ __align__(16) float g_q[Bc*Hc*Tc*HDc];      // (b,h,t,hd) fp32
__device__ __align__(16) float g_ksum[Bc*Hc*HDc];
__device__ __align__(16) float g_gdiag[Hc*HDc];
__device__ __align__(16) float g_bqk[2*Dc];
__device__ __align__(16) __nv_bfloat16 g_x2[Mc*KTOT];        // [hi|hi|lo] of x (bf16)
__device__ __align__(16) __half g_xh[Mc*1024];               // fp16(x)
__device__ __align__(16) __nv_bfloat16 g_w2[2][Dc*KTOT];     // [hi|lo|hi] Wq,Wk
__device__ __align__(16) __half g_wv[Dc*1024];               // fp16(Wv)
__device__ __align__(16) __half g_wo[Dc*1024];               // fp16(Wo)
__device__ __align__(16) __half g_o2h[Mc*1024];              // fp16 attn out
__device__ __align__(16) __nv_bfloat16 g_k2[Bc*Hc*Tc*192];   // [hi|lo|hi] key rows
__device__ __align__(16) __half g_v2t[Bc*Hc*HDc*Tc];         // [bh][d][t] fp16 V^T

// ---------------- PTX helpers ----------------------------------------------
__device__ __forceinline__ uint32_t smem_u32(const void* p) {
    uint32_t a;
    asm("{ .reg .u64 t; cvta.to.shared.u64 t, %1; cvt.u32.u64 %0, t; }" : "=r"(a) : "l"(p));
    return a;
}
#define CP_ASYNC16(sm, gm) \
    asm volatile("cp.async.cg.shared.global [%0], [%1], 16;" :: "r"(sm), "l"(gm))
#define CP_COMMIT() asm volatile("cp.async.commit_group;" ::: "memory")
#define CP_WAIT(n)  asm volatile("cp.async.wait_group %0;" :: "n"(n) : "memory")

__device__ __forceinline__ void ldsm_x4(uint32_t& r0, uint32_t& r1,
                                        uint32_t& r2, uint32_t& r3, uint32_t addr) {
    asm volatile("ldmatrix.sync.aligned.m8n8.x4.shared.b16 {%0,%1,%2,%3}, [%4];"
                 : "=r"(r0), "=r"(r1), "=r"(r2), "=r"(r3) : "r"(addr));
}
__device__ __forceinline__ void mma_bf(float* c, const uint32_t* a, const uint32_t* b) {
    asm volatile(
        "mma.sync.aligned.m16n8k16.row.col.f32.bf16.bf16.f32 "
        "{%0,%1,%2,%3}, {%4,%5,%6,%7}, {%8,%9}, {%0,%1,%2,%3};"
        : "+f"(c[0]), "+f"(c[1]), "+f"(c[2]), "+f"(c[3])
        : "r"(a[0]), "r"(a[1]), "r"(a[2]), "r"(a[3]), "r"(b[0]), "r"(b[1]));
}
__device__ __forceinline__ void mma_hf(float* c, const uint32_t* a, const uint32_t* b) {
    asm volatile(
        "mma.sync.aligned.m16n8k16.row.col.f32.f16.f16.f32 "
        "{%0,%1,%2,%3}, {%4,%5,%6,%7}, {%8,%9}, {%0,%1,%2,%3};"
        : "+f"(c[0]), "+f"(c[1]), "+f"(c[2]), "+f"(c[3])
        : "r"(a[0]), "r"(a[1]), "r"(a[2]), "r"(a[3]), "r"(b[0]), "r"(b[1]));
}
__device__ __forceinline__ uint32_t pkhf(float lo, float hi) {
    uint32_t r;
    asm("cvt.rn.f16x2.f32 %0, %1, %2;" : "=r"(r) : "f"(hi), "f"(lo));
    return r;
}
__device__ __forceinline__ uint32_t h2ex2(uint32_t x) {
    uint32_t r;
    asm("ex2.approx.f16x2 %0, %1;" : "=r"(r) : "r"(x));
    return r;
}

// ---------------------------------------------------------------------------
// One prep kernel: x -> bf16 triple + fp16 plane; Wq/Wk -> bf16 triples;
// Wv/Wo -> fp16 planes; bias concat; gdiag; ksum zero.
// ---------------------------------------------------------------------------
__global__ void prep_all(const float* __restrict__ x,
                         const float* __restrict__ Wq, const float* __restrict__ Wk,
                         const float* __restrict__ Wv, const float* __restrict__ Wo,
                         const float* __restrict__ bq, const float* __restrict__ bk,
                         const float* __restrict__ A, const float* __restrict__ ll) {
    int i = blockIdx.x * blockDim.x + threadIdx.x;
    const int N0 = Mc * 512, NW = Dc * 512;
    if (i < N0) {                               // x: triple + fp16
        float2 v = ((const float2*)x)[i];
        int r = i >> 9, c2 = i & 511;
        __nv_bfloat162 hi, lo;
        hi.x = __float2bfloat16(v.x); hi.y = __float2bfloat16(v.y);
        lo.x = __float2bfloat16(v.x - __bfloat162float(hi.x));
        lo.y = __float2bfloat16(v.y - __bfloat162float(hi.y));
        __nv_bfloat162* d = (__nv_bfloat162*)(g_x2 + (size_t)r * KTOT);
        d[c2] = hi; d[512 + c2] = hi; d[1024 + c2] = lo;
        __half2 h; h.x = __float2half_rn(v.x); h.y = __float2half_rn(v.y);
        ((__half2*)(g_xh + (size_t)r * 1024))[c2] = h;
        return;
    }
    i -= N0;
    if (i < 2 * NW) {                           // Wq / Wk bf16 triple [hi|lo|hi]
        const float* W = (i < NW) ? Wq : Wk;
        __nv_bfloat16* dst = (i < NW) ? g_w2[0] : g_w2[1];
        int j = (i < NW) ? i : i - NW;
        float2 v = ((const float2*)W)[j];
        int r = j >> 9, c2 = j & 511;
        __nv_bfloat162 hi, lo;
        hi.x = __float2bfloat16(v.x); hi.y = __float2bfloat16(v.y);
        lo.x = __float2bfloat16(v.x - __bfloat162float(hi.x));
        lo.y = __float2bfloat16(v.y - __bfloat162float(hi.y));
        __nv_bfloat162* d = (__nv_bfloat162*)(dst + (size_t)r * KTOT);
        d[c2] = hi; d[512 + c2] = lo; d[1024 + c2] = hi;
        return;
    }
    i -= 2 * NW;
    if (i < 2 * NW) {                           // Wv / Wo fp16 plane
        const float* W = (i < NW) ? Wv : Wo;
        __half* dst = (i < NW) ? g_wv : g_wo;
        int j = (i < NW) ? i : i - NW;
        float2 v = ((const float2*)W)[j];
        int r = j >> 9, c2 = j & 511;
        __half2 h; h.x = __float2half_rn(v.x); h.y = __float2half_rn(v.y);
        ((__half2*)(dst + (size_t)r * 1024))[c2] = h;
        return;
    }
    i -= 2 * NW;
    if (i < 2 * Dc) {                           // bias concat
        g_bqk[i] = (i < Dc) ? bq[i] : bk[i - Dc];
        return;
    }
    i -= 2 * Dc;
    if (i < Hc * HDc) {                         // gdiag
        int h = i >> 6, d = i & 63;
        float s = expf(ll[h]);
#pragma unroll
        for (int r = 0; r < 16; r++) {
            float a = A[(h * 16 + r) * HDc + d];
            s = fmaf(a, a, s);
        }
        g_gdiag[i] = s;
        return;
    }
    i -= Hc * HDc;
    if (i < Bc * Hc * HDc) g_ksum[i] = 0.f;     // zero for ksum atomics
}
#define PREP_TOTAL (Mc*512 + 4*(Dc*512) + 2*Dc + Hc*HDc + Bc*Hc*HDc)

// ---------------------------------------------------------------------------
// GEMM body: tile 128x256, warp 64x64, BK=32, 4-stage cp.async.
// mode 0: QK (n0>>10: q fp32 / k triple); mode 1: -> Yext; mode 2: V plane.
// ---------------------------------------------------------------------------
template<int FP16M>
__device__ __forceinline__ void gemm_body(
    uint32_t base, const char* gAb, const char* gWb,
    const float* __restrict__ bias, float* __restrict__ Yext,
    int mode, int ktot, int m0, int n0)
{
    int tid = threadIdx.x, wid = tid >> 5, lane = tid & 31;
    int wm = wid & 1, wn = wid >> 1;

    const char* gA = gAb + (size_t)m0 * ktot * 2;
    const char* gW = gWb + (size_t)n0 * ktot * 2;
    size_t kstride = (size_t)ktot * 2;

    auto load_chunk = [&](int c) {
        uint32_t sa = base + (c % STAGES) * STG_BYTES;
        uint32_t sb = sa + A_STG;
        size_t k0 = (size_t)c * (BK * 2);
#pragma unroll
        for (int it = 0; it < 2; it++) {
            int ch = tid + it * 256;
            int r = ch >> 2, off = (ch & 3) * 16;
            CP_ASYNC16(sa + r * (LDS_ROW*2) + off, gA + r * kstride + k0 + off);
        }
#pragma unroll
        for (int it = 0; it < 4; it++) {
            int ch = tid + it * 256;
            int r = ch >> 2, off = (ch & 3) * 16;
            CP_ASYNC16(sb + r * (LDS_ROW*2) + off, gW + r * kstride + k0 + off);
        }
        CP_COMMIT();
    };

    float acc[4][8][4];
#pragma unroll
    for (int i = 0; i < 4; i++)
#pragma unroll
        for (int j = 0; j < 8; j++)
#pragma unroll
            for (int l = 0; l < 4; l++) acc[i][j][l] = 0.f;

    load_chunk(0);
    load_chunk(1);
    load_chunk(2);

    int a_row = wm * 64 + (lane & 15);
    int a_col8 = (lane >> 4) * 8;
    int b_row = wn * 64 + (lane & 7) + ((lane >> 4) << 3);
    int b_col8 = ((lane >> 3) & 1) * 8;
    int nk = ktot / BK;

#pragma unroll 1
    for (int i = 0; i < nk; i++) {
        CP_WAIT(STAGES - 2);
        __syncthreads();
        if (i + STAGES - 1 < nk) load_chunk(i + STAGES - 1);

        uint32_t sa = base + (i % STAGES) * STG_BYTES;
        uint32_t sb = sa + A_STG;
#pragma unroll
        for (int kk = 0; kk < 2; kk++) {
            uint32_t a[4][4], b[8][2];
#pragma unroll
            for (int mf = 0; mf < 4; mf++)
                ldsm_x4(a[mf][0], a[mf][1], a[mf][2], a[mf][3],
                        sa + ((a_row + mf*16) * LDS_ROW + kk*16 + a_col8) * 2);
#pragma unroll
            for (int np = 0; np < 4; np++)
                ldsm_x4(b[2*np][0], b[2*np][1], b[2*np+1][0], b[2*np+1][1],
                        sb + ((b_row + np*16) * LDS_ROW + kk*16 + b_col8) * 2);
#pragma unroll
            for (int mf = 0; mf < 4; mf++)
#pragma unroll
                for (int nf = 0; nf < 8; nf++) {
                    if (FP16M) mma_hf(acc[mf][nf], a[mf], b[nf]);
                    else       mma_bf(acc[mf][nf], a[mf], b[nf]);
                }
        }
    }

    int proj = n0 >> 10;
#pragma unroll
    for (int mf = 0; mf < 4; mf++) {
#pragma unroll
        for (int nf = 0; nf < 8; nf++) {
            int m = m0 + wm*64 + mf*16 + (lane >> 2);
            int n = n0 + wn*64 + nf*8 + 2*(lane & 3);
            float b0 = bias[n], b1 = bias[n+1];
#pragma unroll
            for (int half = 0; half < 2; half++) {
                int mm = m + half * 8;
                float v0 = acc[mf][nf][half*2+0] + b0;
                float v1 = acc[mf][nf][half*2+1] + b1;
                int bb = mm >> 11, t = mm & 2047;
                int nn = n & 1023;
                int h = nn >> 6, d = nn & 63;
                int bh = bb * Hc + h;
                if (mode == 1) {
                    *(float2*)(Yext + (size_t)mm * Dc + n) = make_float2(v0, v1);
                } else if (mode == 2) {
                    __half* pbase = g_v2t + (size_t)bh * HDc * Tc;
                    pbase[(size_t)d * Tc + t]     = __float2half_rn(v0);
                    pbase[(size_t)(d+1) * Tc + t] = __float2half_rn(v1);
                } else if (proj == 0) {
                    *(float2*)(g_q + ((size_t)bh * Tc + t) * HDc + d) =
                        make_float2(v0, v1);
                } else {
                    __nv_bfloat16 h0 = __float2bfloat16(v0);
                    __nv_bfloat16 l0 = __float2bfloat16(v0 - __bfloat162float(h0));
                    __nv_bfloat16 h1 = __float2bfloat16(v1);
                    __nv_bfloat16 l1 = __float2bfloat16(v1 - __bfloat162float(h1));
                    __nv_bfloat16* row = g_k2 + ((size_t)bh * Tc + t) * 192;
                    row[d] = h0;   row[d+1] = h1;
                    row[64+d] = l0; row[64+d+1] = l1;
                    row[128+d] = h0; row[128+d+1] = h1;
                }
            }
        }
    }
}

// fused QKV: y<8 -> QK bf16 3-product (K=3072); y>=8 -> V fp16 (K=1024)
__global__ __launch_bounds__(256)
void qkv_fused(const float* __restrict__ bv) {
    extern __shared__ __align__(16) char dsmem[];
    uint32_t base = smem_u32(dsmem);
    int by = blockIdx.y;
    if (by < 8)
        gemm_body<0>(base, (const char*)g_x2, (const char*)g_w2,
                     g_bqk, nullptr, 0, KTOT, blockIdx.x * BM, by * 256);
    else
        gemm_body<1>(base, (const char*)g_xh, (const char*)g_wv,
                     bv, nullptr, 2, 1024, blockIdx.x * BM, (by - 8) * 256);
}

// final projection: out = o2h @ Wo^T + bo  (fp16 single product, K=1024)
__global__ __launch_bounds__(256)
void gemm_o(const float* __restrict__ bo, float* __restrict__ out) {
    extern __shared__ __align__(16) char dsmem[];
    uint32_t base = smem_u32(dsmem);
    gemm_body<1>(base, (const char*)g_o2h, (const char*)g_wo,
                 bo, out, 1, 1024, blockIdx.x * BM, blockIdx.y * 256);
}

// ---------------------------------------------------------------------------
// ksum over many blocks with atomics (g_ksum zeroed by prep_all)
// ---------------------------------------------------------------------------
__global__ __launch_bounds__(256) void ksum2_kernel() {
    __shared__ float red[256];
    int bh = blockIdx.x;
    int seg = blockIdx.y;
    int d = threadIdx.x & 63, chunk = threadIdx.x >> 6;
    const __nv_bfloat16* base = g_k2 + (size_t)bh * Tc * 192;
    float s = 0.f;
    int t0 = seg * 256 + chunk * 64;
    for (int t = t0; t < t0 + 64; t++) {
        const __nv_bfloat16* row = base + (size_t)t * 192;
        s += __bfloat162float(row[d]) + __bfloat162float(row[64 + d]);
    }
    red[threadIdx.x] = s;
    __syncthreads();
    if (chunk == 0)
        atomicAdd(&g_ksum[bh * HDc + d],
                  red[d] + red[64 + d] + red[128 + d] + red[192 + d]);
}

// ---------------------------------------------------------------------------
// Tensor-core flash attention (round-8 structure). Softmax cost reduced:
//  - P = exp computed directly in fp16 via ex2.approx.f16x2 (half the MUFU)
//  - row sums accumulated by an extra ones-column mma (sum_acc), removing
//    the per-tile sum reduction chain + shuffles entirely. Since the SAME
//    fp16 P feeds numerator (PV) and denominator (sum), normalization
//    cancels common-mode rounding of P.
// ---------------------------------------------------------------------------
__global__ __launch_bounds__(256, 1)
void attn_tc() {
    extern __shared__ __align__(16) char asmem[];
    uint32_t sgs = smem_u32(asmem);
    uint32_t k2s = sgs + SG_BYTES_A;
    uint32_t vts = k2s + 2 * K2STG;
    __nv_bfloat16* sg_sm = (__nv_bfloat16*)asmem;

    int tid = threadIdx.x, wid = tid >> 5, lane = tid & 31;
    int bh = blockIdx.y, h = bh & 15, b = bh >> 4;
    int q0 = blockIdx.x * AT_M;

    const float*         q_g = g_q   + ((size_t)bh * Tc + q0) * HDc;
    const __nv_bfloat16* k_g = g_k2  + (size_t)bh * Tc * 192;
    const __half*        v_g = g_v2t + (size_t)bh * HDc * Tc;
    const float*         ks  = g_ksum + bh * HDc;
    const float*         gd  = g_gdiag + h * HDc;

    auto load_tile = [&](int ti) {
        int st = ti & 1;
        int j0 = ti * 64;
        uint32_t kd = k2s + st * K2STG;
        uint32_t vd = vts + st * VTSTG;
#pragma unroll
        for (int it = 0; it < 6; it++) {          // K: 64 x 192 bf16
            int id = tid + it * 256;
            int r = id / 24, c = id % 24;
            CP_ASYNC16(kd + r * (LDSA*2) + c * 16,
                       (const char*)(k_g + (size_t)(j0 + r) * 192 + c * 8));
        }
#pragma unroll
        for (int it = 0; it < 2; it++) {          // V^T: 64 x 64 fp16
            int id = tid + it * 256;
            int r = id >> 3, c = id & 7;
            CP_ASYNC16(vd + r * (LDV*2) + c * 16,
                       (const char*)(v_g + (size_t)r * Tc + j0 + c * 8));
        }
        CP_COMMIT();
    };

    load_tile(0);

    // compute Sg tile in-kernel: [hi|hi|lo] rows of LDSA
    for (int idx = tid; idx < 128 * 64; idx += 256) {
        int r = idx >> 6, d = idx & 63;
        float sg = (2048.0f * q_g[r * HDc + d] - ks[d]) * gd[d];
        __nv_bfloat16 hi = __float2bfloat16(sg);
        __nv_bfloat16 lo = __float2bfloat16(sg - __bfloat162float(hi));
        __nv_bfloat16* row = sg_sm + r * LDSA;
        row[d] = hi; row[64 + d] = hi; row[128 + d] = lo;
    }
    __syncthreads();

    uint32_t aq[12][4];
    {
        int arow = wid * 16 + (lane & 15);
        int acol = (lane >> 4) * 8;
#pragma unroll
        for (int kc = 0; kc < 12; kc++)
            ldsm_x4(aq[kc][0], aq[kc][1], aq[kc][2], aq[kc][3],
                    sgs + (arow * LDSA + kc * 16 + acol) * 2);
    }

    float o_acc[8][4];
#pragma unroll
    for (int nf = 0; nf < 8; nf++)
#pragma unroll
        for (int l = 0; l < 4; l++) o_acc[nf][l] = 0.f;
    float sum_acc[4] = {0.f, 0.f, 0.f, 0.f};
    float m0 = -CUDART_INF_F, m1 = -CUDART_INF_F;

    const uint32_t bones[2] = {0x3C003C00u, 0x3C003C00u};  // fp16 ones

    int brow = (lane & 7) + ((lane >> 4) << 3);
    int bcol8 = ((lane >> 3) & 1) * 8;

#pragma unroll 1
    for (int ti = 0; ti < 32; ti++) {
        if (ti + 1 < 32) { load_tile(ti + 1); CP_WAIT(1); }
        else CP_WAIT(0);
        __syncthreads();
        int st = ti & 1;
        uint32_t kd = k2s + st * K2STG;
        uint32_t vd = vts + st * VTSTG;

        // ---- QK: s[8][4] over 12 bf16 k16 chunks ----
        float s[8][4];
#pragma unroll
        for (int nf = 0; nf < 8; nf++)
#pragma unroll
            for (int l = 0; l < 4; l++) s[nf][l] = 0.f;
#pragma unroll
        for (int kc = 0; kc < 12; kc++) {
            uint32_t bq[8][2];
#pragma unroll
            for (int np = 0; np < 4; np++)
                ldsm_x4(bq[2*np][0], bq[2*np][1], bq[2*np+1][0], bq[2*np+1][1],
                        kd + ((np*16 + brow) * LDSA + kc*16 + bcol8) * 2);
#pragma unroll
            for (int nf = 0; nf < 8; nf++)
                mma_bf(s[nf], aq[kc], bq[nf]);
        }

        // ---- row max (only reduction left) ----
        float rm0 = -CUDART_INF_F, rm1 = -CUDART_INF_F;
#pragma unroll
        for (int nf = 0; nf < 8; nf++) {
            rm0 = fmaxf(rm0, fmaxf(s[nf][0], s[nf][1]));
            rm1 = fmaxf(rm1, fmaxf(s[nf][2], s[nf][3]));
        }
        rm0 = fmaxf(rm0, __shfl_xor_sync(0xffffffffu, rm0, 1));
        rm0 = fmaxf(rm0, __shfl_xor_sync(0xffffffffu, rm0, 2));
        rm1 = fmaxf(rm1, __shfl_xor_sync(0xffffffffu, rm1, 1));
        rm1 = fmaxf(rm1, __shfl_xor_sync(0xffffffffu, rm1, 2));
        float mn0 = fmaxf(m0, rm0), mn1 = fmaxf(m1, rm1);
        float sc0 = __expf(m0 - mn0), sc1 = __expf(m1 - mn1);
        m0 = mn0; m1 = mn1;
        float mnl0 = mn0 * L2E, mnl1 = mn1 * L2E;

        // rescale running numerator and denominator
#pragma unroll
        for (int nf = 0; nf < 8; nf++) {
            o_acc[nf][0] *= sc0; o_acc[nf][1] *= sc0;
            o_acc[nf][2] *= sc1; o_acc[nf][3] *= sc1;
        }
        sum_acc[0] *= sc0; sum_acc[1] *= sc0;
        sum_acc[2] *= sc1; sum_acc[3] *= sc1;

        // ---- P = 2^(s*log2e - mn*log2e) in fp16, + ones-column row sum ----
        uint32_t Ahi[4][4];
#pragma unroll
        for (int kc = 0; kc < 4; kc++) {
            int f0 = 2*kc, f1 = 2*kc + 1;
            Ahi[kc][0] = h2ex2(pkhf(fmaf(s[f0][0], L2E, -mnl0),
                                    fmaf(s[f0][1], L2E, -mnl0)));
            Ahi[kc][1] = h2ex2(pkhf(fmaf(s[f0][2], L2E, -mnl1),
                                    fmaf(s[f0][3], L2E, -mnl1)));
            Ahi[kc][2] = h2ex2(pkhf(fmaf(s[f1][0], L2E, -mnl0),
                                    fmaf(s[f1][1], L2E, -mnl0)));
            Ahi[kc][3] = h2ex2(pkhf(fmaf(s[f1][2], L2E, -mnl1),
                                    fmaf(s[f1][3], L2E, -mnl1)));
            mma_hf(sum_acc, Ahi[kc], bones);
        }

        // ---- PV: o += P * Vhi ----
#pragma unroll
        for (int kc = 0; kc < 4; kc++) {
            uint32_t bvh[8][2];
#pragma unroll
            for (int np = 0; np < 4; np++)
                ldsm_x4(bvh[2*np][0], bvh[2*np][1], bvh[2*np+1][0], bvh[2*np+1][1],
                        vd + ((np*16 + brow) * LDV + kc*16 + bcol8) * 2);
#pragma unroll
            for (int nf = 0; nf < 8; nf++)
                mma_hf(o_acc[nf], Ahi[kc], bvh[nf]);
        }
        __syncthreads();
    }

    // epilogue: every lane holds its rows' sums (cols identical, no shuffle)
    float inv0 = 1.0f / sum_acc[0], inv1 = 1.0f / sum_acc[2];
    int r0 = q0 + wid * 16 + (lane >> 2);
    int r1 = r0 + 8;
    __half* row0 = g_o2h + (size_t)(b * Tc + r0) * 1024;
    __half* row1 = g_o2h + (size_t)(b * Tc + r1) * 1024;
#pragma unroll
    for (int nf = 0; nf < 8; nf++) {
        int n = h * HDc + nf * 8 + 2 * (lane & 3);
        *(uint32_t*)(row0 + n) = pkhf(o_acc[nf][0] * inv0, o_acc[nf][1] * inv0);
        *(uint32_t*)(row1 + n) = pkhf(o_acc[nf][2] * inv1, o_acc[nf][3] * inv1);
    }
}

// ---------------------------------------------------------------------------
extern "C" void kernel_launch(void* const* d_in, const int* in_sizes, int n_in,
                              void* d_out, int out_size) {
    const float* x   = (const float*)d_in[0];
    const float* Wq  = (const float*)d_in[1];
    const float* bq  = (const float*)d_in[2];
    const float* Wk  = (const float*)d_in[3];
    const float* bk  = (const float*)d_in[4];
    const float* Wv  = (const float*)d_in[5];
    const float* bv  = (const float*)d_in[6];
    const float* Wo  = (const float*)d_in[7];
    const float* bo  = (const float*)d_in[8];
    const float* A   = (const float*)d_in[9];
    const float* ll  = (const float*)d_in[10];
    float* out = (float*)d_out;

    cudaFuncSetAttribute(qkv_fused, cudaFuncAttributeMaxDynamicSharedMemorySize, SMEM_DYN);
    cudaFuncSetAttribute(gemm_o,    cudaFuncAttributeMaxDynamicSharedMemorySize, SMEM_DYN);
    cudaFuncSetAttribute(attn_tc,   cudaFuncAttributeMaxDynamicSharedMemorySize, ASMEM);

    prep_all<<<(PREP_TOTAL + 255)/256, 256>>>(x, Wq, Wk, Wv, Wo, bq, bk, A, ll);

    // fused QK (bf16 3-product) + V (fp16 single product)
    qkv_fused<<<dim3(Mc/BM, 12), 256, SMEM_DYN>>>(bv);

    ksum2_kernel<<<dim3(Bc*Hc, 8), 256>>>();

    attn_tc<<<dim3(Tc / AT_M, Bc * Hc), 256, ASMEM>>>();

    gemm_o<<<dim3(Mc/BM, Dc/BN), 256, SMEM_DYN>>>(bo, out);
}